// round 12
// baseline (speedup 1.0000x reference)
#include <cuda_runtime.h>
#include <cuda_fp16.h>
#include <cstdint>

// ---------------- problem constants ----------------
#define NB 256     // batch
#define NT 256     // timesteps
#define D_T 300
#define D_A 74
#define D_V 35
#define DD 409
#define KP 416     // padded D (multiple of 16)
#define NH 1024    // hidden
#define NG 4096    // 4*H
#define NC 512     // MLP cell

#define NCTA_REC 128
#define NGRP 64                // CTAs per barrier group (one per batch half)
#define APITCH 80              // halves; 40 words ≡ 8 (mod 32) -> conflict-free v2 frags
#define BPITCH 1040            // halves; 520 words ≡ 8 (mod 32) -> conflict-free v2 frags
#define ASTAGE (128 * APITCH)  // halves per A stage
#define NASTG 4
#define REC_SMEM (NASTG * ASTAGE * 2 + 64 * BPITCH * 2)   // 81920 + 133120 = 215040 B

#define XAPITCH 48             // halves; 24 words ≡ 24 (mod 32) -> conflict-free v2 frags
#define XA_STAGE (128 * XAPITCH)
#define XA_SMEM (6 * XA_STAGE * 2)                        // 73728 B (3 stages x (A+B))

// ---------------- device scratch (no allocs allowed) ----------------
__device__ __half g_Xh[(size_t)NB * NT * KP];       // fp16, K-permuted, row = t*NB+b
__device__ __half g_Wihh[(size_t)NG * KP];          // fp16, K-permuted, zero padded
__device__ __half g_Whhh[(size_t)NG * NH];          // fp16, K-permuted
__device__ float  g_bias[NG];                       // b_ih + b_hh
__device__ __half g_XGh[(size_t)NT * NB * NG];      // input gates (logical cols)
__device__ __half g_hbuf[2][NB * NH];               // double-buffered h (fp16, K-permuted)
__device__ float  g_hidden[NB * NC];
__device__ unsigned g_bar_arrive[2];
__device__ unsigned g_bar_gen[2];

// ---------------- K-permutation (word interleave within 16-half groups) ----------------
// stored word position p <- logical word w:  p = (w<4) ? 2w : 2(w-4)+1
__device__ __forceinline__ int perm_src(int c) {   // stored col -> logical col
    const int p = (c & 15) >> 1, e = c & 1;
    const int w = (p & 1) ? (p >> 1) + 4 : (p >> 1);
    return (c & ~15) | (w << 1) | e;
}
__device__ __forceinline__ int perm_dst(int d) {   // logical col -> stored col
    const int w = (d & 15) >> 1, e = d & 1;
    const int p = (w < 4) ? (w << 1) : (((w - 4) << 1) + 1);
    return (d & ~15) | (p << 1) | e;
}

// ---------------- helpers ----------------
__device__ __forceinline__ void mma16(float* c, uint32_t a0, uint32_t a1, uint32_t a2,
                                      uint32_t a3, uint32_t b0, uint32_t b1) {
    asm("mma.sync.aligned.m16n8k16.row.col.f32.f16.f16.f32 "
        "{%0,%1,%2,%3}, {%4,%5,%6,%7}, {%8,%9}, {%0,%1,%2,%3};\n"
        : "+f"(c[0]), "+f"(c[1]), "+f"(c[2]), "+f"(c[3])
        : "r"(a0), "r"(a1), "r"(a2), "r"(a3), "r"(b0), "r"(b1));
}

__device__ __forceinline__ float fast_sig(float x) {
    return __fdividef(1.f, 1.f + __expf(-x));
}
__device__ __forceinline__ float fast_tanh(float x) {
    return 1.f - __fdividef(2.f, __expf(2.f * x) + 1.f);
}

__device__ __forceinline__ uint32_t smem_u32(const void* p) {
    uint32_t a;
    asm("{ .reg .u64 t; cvta.to.shared.u64 t, %1; cvt.u32.u64 %0, t; }" : "=r"(a) : "l"(p));
    return a;
}

// ---------------- packing / init (write K-permuted layouts) ----------------
__global__ void pack_x(const float* __restrict__ xt, const float* __restrict__ xa,
                       const float* __restrict__ xv) {
    size_t idx = (size_t)blockIdx.x * blockDim.x + threadIdx.x;
    int c = (int)(idx % KP);
    size_t r = idx / KP;             // r = t*NB + b
    int t = (int)(r / NB), b = (int)(r % NB);
    const int d = perm_src(c);       // logical feature index
    float v = 0.f;
    if (d < D_T)            v = xt[((size_t)b * NT + t) * D_T + d];
    else if (d < D_T + D_A) v = xa[((size_t)b * NT + t) * D_A + (d - D_T)];
    else if (d < DD)        v = xv[((size_t)b * NT + t) * D_V + (d - D_T - D_A)];
    g_Xh[idx] = __float2half(v);
}

__global__ void pack_wih(const float* __restrict__ W) {
    size_t idx = (size_t)blockIdx.x * blockDim.x + threadIdx.x;
    int c = (int)(idx % KP);
    size_t row = idx / KP;
    const int d = perm_src(c);
    float v = (d < DD) ? W[row * DD + d] : 0.f;
    g_Wihh[idx] = __float2half(v);
}

__global__ void pack_whh(const float* __restrict__ W) {
    size_t idx = (size_t)blockIdx.x * blockDim.x + threadIdx.x;
    int c = (int)(idx % NH);
    size_t row = idx / NH;
    g_Whhh[idx] = __float2half(W[row * NH + perm_src(c)]);
}

__global__ void pack_bias(const float* __restrict__ bih, const float* __restrict__ bhh) {
    int i = blockIdx.x * blockDim.x + threadIdx.x;
    g_bias[i] = bih[i] + bhh[i];
}

__global__ void zero_state() {
    int i = blockIdx.x * blockDim.x + threadIdx.x;
    ((__half*)g_hbuf)[i] = __float2half(0.f);
    if (i < 2) { g_bar_arrive[i] = 0u; g_bar_gen[i] = 0u; }
}

// ---------------- Phase A: XG = X @ Wih^T + bias (fp16, 3-stage cp.async, BK=32) ----------------
// M=65536, N=4096, K=416. BM=128, BN=128, BK=32, 256 threads (2x4 warps, 64x32 tiles).
__global__ __launch_bounds__(256, 2) void gemm_xg() {
    extern __shared__ __align__(16) __half dsmA[];
    __half (*As)[128][XAPITCH] = (__half (*)[128][XAPITCH])dsmA;            // 3 stages
    __half (*Bs)[128][XAPITCH] = (__half (*)[128][XAPITCH])(dsmA + 3 * XA_STAGE);

    const int tid = threadIdx.x;
    const int warp = tid >> 5, lane = tid & 31;
    const int gid = lane >> 2, tig = lane & 3;
    const int wm = warp >> 2, wn = warp & 3;
    const int mbase = blockIdx.y * 128;
    const int nbase = blockIdx.x * 128;

    float acc[4][4][4];
#pragma unroll
    for (int i = 0; i < 4; i++)
#pragma unroll
        for (int j = 0; j < 4; j++)
#pragma unroll
            for (int k = 0; k < 4; k++) acc[i][j][k] = 0.f;

    // cp.async plan: 4 x 16B segments per thread (A: 512 segs, B: 512 segs)
    const __half* srcP[4];
    uint32_t dstP[4];
#pragma unroll
    for (int i = 0; i < 4; i++) {
        const int seg = tid + 256 * i;
        if (seg < 512) {
            const int row = seg >> 2, q = seg & 3;
            srcP[i] = g_Xh + (size_t)(mbase + row) * KP + q * 8;
            dstP[i] = smem_u32(&As[0][row][q * 8]);
        } else {
            const int s2 = seg - 512;
            const int row = s2 >> 2, q = s2 & 3;
            srcP[i] = g_Wihh + (size_t)(nbase + row) * KP + q * 8;
            dstP[i] = smem_u32(&Bs[0][row][q * 8]);
        }
    }
    const uint32_t stB = XA_STAGE * 2;   // bytes per stage

#define CPXA(kc_) do {                                                              \
    _Pragma("unroll")                                                               \
    for (int i_ = 0; i_ < 4; i_++)                                                  \
        asm volatile("cp.async.cg.shared.global [%0], [%1], 16;\n"                  \
                     :: "r"(dstP[i_] + ((kc_) % 3) * stB), "l"(srcP[i_] + (kc_) * 32)); \
    asm volatile("cp.async.commit_group;\n" ::: "memory");                          \
} while (0)

    CPXA(0);
    CPXA(1);

    const int NKA = KP / 32;   // 13
    for (int kc = 0; kc < NKA; kc++) {
        if (kc + 2 < NKA) asm volatile("cp.async.wait_group 1;\n" ::: "memory");
        else              asm volatile("cp.async.wait_group 0;\n" ::: "memory");
        __syncthreads();
        if (kc + 2 < NKA) CPXA(kc + 2);

        const int cur = kc % 3;
#pragma unroll
        for (int s = 0; s < 2; s++) {
            const int ko = s * 16;
            uint2 a02[4], a13[4], bf[4];
#pragma unroll
            for (int mt = 0; mt < 4; mt++) {
                const int rr = wm * 64 + mt * 16 + gid;
                a02[mt] = *(const uint2*)(&As[cur][rr][ko + 4 * tig]);
                a13[mt] = *(const uint2*)(&As[cur][rr + 8][ko + 4 * tig]);
            }
#pragma unroll
            for (int nt = 0; nt < 4; nt++) {
                const int nn = wn * 32 + nt * 8 + gid;
                bf[nt] = *(const uint2*)(&Bs[cur][nn][ko + 4 * tig]);
            }
#pragma unroll
            for (int mt = 0; mt < 4; mt++)
#pragma unroll
                for (int nt = 0; nt < 4; nt++)
                    mma16(acc[mt][nt], a02[mt].x, a13[mt].x, a02[mt].y, a13[mt].y,
                          bf[nt].x, bf[nt].y);
        }
    }
#undef CPXA

#pragma unroll
    for (int mt = 0; mt < 4; mt++) {
        const int row = mbase + wm * 64 + mt * 16 + gid;
#pragma unroll
        for (int nt = 0; nt < 4; nt++) {
            const int col = nbase + wn * 32 + nt * 8 + 2 * tig;
            const float b0 = g_bias[col], b1 = g_bias[col + 1];
            __half2 v0 = __floats2half2_rn(acc[mt][nt][0] + b0, acc[mt][nt][1] + b1);
            __half2 v1 = __floats2half2_rn(acc[mt][nt][2] + b0, acc[mt][nt][3] + b1);
            *(__half2*)(&g_XGh[(size_t)row * NG + col]) = v0;
            *(__half2*)(&g_XGh[(size_t)(row + 8) * NG + col]) = v1;
        }
    }
}

// ---------------- persistent recurrence kernel ----------------
// 128 CTAs, 512 threads (16 warps: wm 0..7 x wn 0..1). CTA = 128 batch x 16 h-cols.
// Whh slice resident in smem; c in registers; h double-buffered in gmem (K-permuted);
// v2 fragment loads; per-batch-half grid barrier (64 CTAs each).
__global__ __launch_bounds__(512, 1) void lstm_rec() {
    extern __shared__ __align__(16) __half dsm[];
    __half (*As)[128][APITCH] = (__half (*)[128][APITCH])dsm;          // NASTG stages
    __half (*Bs)[BPITCH] = (__half (*)[BPITCH])(dsm + NASTG * ASTAGE);

    const int tid = threadIdx.x;
    const int warp = tid >> 5, lane = tid & 31;
    const int gid = lane >> 2, tig = lane & 3;
    const int wm = warp >> 1;          // 0..7 : 16-row slices
    const int wn = warp & 1;           // 0..1 : 8 h-cols each
    const int blk = blockIdx.x;
    const int nbase = (blk & 63) * 16;     // h-col base (logical)
    const int mbase = (blk >> 6) * 128;    // batch base
    const int grp = blk >> 6;              // barrier group

    // ---- load Whh slice into smem once (64 rows x 1024 halves, K-permuted src) ----
    for (int q = tid; q < 64 * 128; q += 512) {
        const int j = q >> 7, seg = q & 127;          // j: gate*16+col
        const int gate = j >> 4, col = nbase + (j & 15);
        *(uint4*)(&Bs[j][seg * 8]) =
            *(const uint4*)(g_Whhh + (size_t)(gate * NH + col) * NH + seg * 8);
    }
    __syncthreads();

    // ---- cp.async plan for A: 2 x 16B segments per thread per 64-half chunk ----
    uint32_t dstA[2];
    size_t aoff[2];
#pragma unroll
    for (int i = 0; i < 2; i++) {
        const int seg = tid + 512 * i;                // 0..1023
        const int row = seg >> 3, q = seg & 7;        // 8 segs of 16B per row
        dstA[i] = smem_u32(&As[0][row][q * 8]);
        aoff[i] = (size_t)(mbase + row) * NH + q * 8;
    }
    const uint32_t stA = ASTAGE * 2;   // bytes per A stage

    const int rr0 = wm * 16 + gid;
    const int row0 = mbase + rr0;
    const int nc = nbase + wn * 8 + 2 * tig;               // logical col (even)
    const int ncs = nbase + 4 * tig + 2 * wn;              // stored col of (nc, nc+1)

    float creg[4];
#pragma unroll
    for (int p = 0; p < 4; p++) creg[p] = 0.f;

    for (int t = 0; t < NT; t++) {
        const __half* hR = g_hbuf[t & 1];
        __half* hW = g_hbuf[(t + 1) & 1];

        // prefetch XG gate values (hidden under K-loop)
        __half2 xg0[4], xg1[4];
        {
            const size_t b0 = ((size_t)t * NB + row0) * NG + nc;
            const size_t b1 = ((size_t)t * NB + row0 + 8) * NG + nc;
#pragma unroll
            for (int g = 0; g < 4; g++) {
                xg0[g] = __ldg((const __half2*)&g_XGh[b0 + g * 1024]);
                xg1[g] = __ldg((const __half2*)&g_XGh[b1 + g * 1024]);
            }
        }

#define CPA(kc_) do {                                                               \
        _Pragma("unroll")                                                           \
        for (int i_ = 0; i_ < 2; i_++)                                              \
            asm volatile("cp.async.cg.shared.global [%0], [%1], 16;\n"              \
                         :: "r"(dstA[i_] + ((kc_) % NASTG) * stA),                  \
                            "l"(hR + aoff[i_] + (kc_) * 64));                       \
        asm volatile("cp.async.commit_group;\n" ::: "memory");                      \
} while (0)

        CPA(0);
        CPA(1);
        CPA(2);

        float acc[4][4];
#pragma unroll
        for (int g = 0; g < 4; g++)
#pragma unroll
            for (int k = 0; k < 4; k++) acc[g][k] = 0.f;

        const int NITER = 16;
        for (int kc = 0; kc < NITER; kc++) {
            if (kc + 3 <= NITER) asm volatile("cp.async.wait_group 2;\n" ::: "memory");
            else if (kc + 2 == NITER) asm volatile("cp.async.wait_group 1;\n" ::: "memory");
            else                 asm volatile("cp.async.wait_group 0;\n" ::: "memory");
            __syncthreads();
            if (kc + 3 < NITER) CPA(kc + 3);

            const int cur = kc % NASTG;
#pragma unroll
            for (int s = 0; s < 4; s++) {
                const int ko = s * 16;
                const uint2 a02 = *(const uint2*)(&As[cur][rr0][ko + 4 * tig]);
                const uint2 a13 = *(const uint2*)(&As[cur][rr0 + 8][ko + 4 * tig]);
                const int kg = kc * 64 + ko;
#pragma unroll
                for (int g = 0; g < 4; g++) {
                    const int nb = g * 16 + wn * 8 + gid;
                    const uint2 bf = *(const uint2*)(&Bs[nb][kg + 4 * tig]);
                    mma16(acc[g], a02.x, a13.x, a02.y, a13.y, bf.x, bf.y);
                }
            }
        }
#undef CPA

        // ---- pointwise LSTM update (all 4 gates thread-local) ----
        {
            float hv[4];
#pragma unroll
            for (int p = 0; p < 4; p++) {
                const __half2* xg = (p < 2) ? xg0 : xg1;
                const int e = p & 1;
                const float xi = e ? __high2float(xg[0]) : __low2float(xg[0]);
                const float xf = e ? __high2float(xg[1]) : __low2float(xg[1]);
                const float xs = e ? __high2float(xg[2]) : __low2float(xg[2]);
                const float xo = e ? __high2float(xg[3]) : __low2float(xg[3]);
                const float iv = fast_sig(acc[0][p] + xi);
                const float fv = fast_sig(acc[1][p] + xf);
                const float gv = fast_tanh(acc[2][p] + xs);
                const float ov = fast_sig(acc[3][p] + xo);
                const float cn = fv * creg[p] + iv * gv;
                creg[p] = cn;
                hv[p] = ov * fast_tanh(cn);
            }
            // store at K-permuted position so next step's cp.async reads frag-ready data
            *(__half2*)(&hW[(size_t)row0 * NH + ncs]) = __floats2half2_rn(hv[0], hv[1]);
            *(__half2*)(&hW[(size_t)(row0 + 8) * NH + ncs]) = __floats2half2_rn(hv[2], hv[3]);
        }

        // ---- per-batch-half grid barrier (64 CTAs; skip after last step) ----
        if (t + 1 < NT) {
            __syncthreads();
            if (tid == 0) {
                __threadfence();
                const unsigned old = atomicAdd(&g_bar_arrive[grp], 1u);
                if (old == NGRP - 1) {
                    g_bar_arrive[grp] = 0u;
                    __threadfence();
                    atomicAdd(&g_bar_gen[grp], 1u);
                } else {
                    const unsigned target = (unsigned)(t + 1);
                    while (*((volatile unsigned*)&g_bar_gen[grp]) < target) {}
                }
                __threadfence();
            }
            __syncthreads();
        }
    }
}

// ---------------- MLP head ----------------
__global__ void mlp1(const float* __restrict__ W1, const float* __restrict__ b1) {
    const int b = blockIdx.y * 32 + threadIdx.x;
    const int c = blockIdx.x * 8 + threadIdx.y;
    const __half* hr = g_hbuf[0] + (size_t)b * NH;   // final h lands in buffer 0 (NT even)
    const float* wr = W1 + (size_t)c * NH;
    float s = 0.f;
#pragma unroll 4
    for (int k = 0; k < NH; k++) s += __half2float(hr[perm_dst(k)]) * wr[k];
    g_hidden[(size_t)b * NC + c] = fmaxf(s + b1[c], 0.f);
}

__global__ void mlp2(const float* __restrict__ W2, const float* __restrict__ b2,
                     float* __restrict__ out) {
    const int b = blockIdx.x;
    const int tid = threadIdx.x;  // 128
    float s = 0.f;
    for (int c = tid; c < NC; c += 128) s += g_hidden[b * NC + c] * W2[c];
#pragma unroll
    for (int o = 16; o > 0; o >>= 1) s += __shfl_down_sync(0xffffffffu, s, o);
    __shared__ float red[4];
    if ((tid & 31) == 0) red[tid >> 5] = s;
    __syncthreads();
    if (tid == 0) out[b] = red[0] + red[1] + red[2] + red[3] + b2[0];
}

// ---------------- launch ----------------
extern "C" void kernel_launch(void* const* d_in, const int* in_sizes, int n_in,
                              void* d_out, int out_size) {
    const float* x_text = (const float*)d_in[0];
    const float* x_audio = (const float*)d_in[1];
    const float* x_vision = (const float*)d_in[2];
    const float* W_ih = (const float*)d_in[3];
    const float* W_hh = (const float*)d_in[4];
    const float* b_ih = (const float*)d_in[5];
    const float* b_hh = (const float*)d_in[6];
    const float* W1 = (const float*)d_in[7];
    const float* b1 = (const float*)d_in[8];
    const float* W2 = (const float*)d_in[9];
    const float* b2 = (const float*)d_in[10];
    float* out = (float*)d_out;

    static int s_attr_done = 0;
    if (!s_attr_done) {
        cudaFuncSetAttribute(lstm_rec, cudaFuncAttributeMaxDynamicSharedMemorySize,
                             REC_SMEM);
        cudaFuncSetAttribute(gemm_xg, cudaFuncAttributeMaxDynamicSharedMemorySize,
                             XA_SMEM);
        s_attr_done = 1;
    }

    pack_x<<<(int)(((size_t)NB * NT * KP) / 256), 256>>>(x_text, x_audio, x_vision);
    pack_wih<<<(NG * KP) / 256, 256>>>(W_ih);
    pack_whh<<<(NG * NH) / 256, 256>>>(W_hh);
    pack_bias<<<NG / 256, 256>>>(b_ih, b_hh);
    zero_state<<<(2 * NB * NH) / 256, 256>>>();

    gemm_xg<<<dim3(32, 512), 256, XA_SMEM>>>();

    lstm_rec<<<NCTA_REC, 512, REC_SMEM>>>();

    mlp1<<<dim3(64, 8), dim3(32, 8)>>>(W1, b1);
    mlp2<<<NB, 128>>>(W2, b2, out);
}

// round 16
// speedup vs baseline: 1.3915x; 1.3915x over previous
#include <cuda_runtime.h>
#include <cuda_fp16.h>
#include <cstdint>

// ---------------- problem constants ----------------
#define NB 256     // batch
#define NT 256     // timesteps
#define D_T 300
#define D_A 74
#define D_V 35
#define DD 409
#define KP 416     // padded D (multiple of 16)
#define NH 1024    // hidden
#define NG 4096    // 4*H
#define NC 512     // MLP cell

#define NCTA_REC 128
#define NGRP 64                // CTAs per barrier group (one group per batch half)
#define BPITCH 1032            // halves; 516 words ≡ 4 (mod 32) -> conflict-free B frags
#define APITCH 72              // halves; 36 words ≡ 4 (mod 32) -> conflict-free A frags
#define ASTAGE (128 * APITCH)  // halves per A stage
#define NASTG 4
#define REC_SMEM (NASTG * ASTAGE * 2 + 64 * BPITCH * 2)   // 73728 + 132096 = 205824 B

#define XA_STAGE (128 * 40)                            // halves per phase-A stage (A or B)
#define XA_SMEM (6 * XA_STAGE * 2)                     // 61440 B (3 stages x (A+B))

// ---------------- device scratch (no allocs allowed) ----------------
__device__ __half g_Xh[(size_t)NB * NT * KP];
__device__ __half g_Wihh[(size_t)NG * KP];
__device__ __half g_Whhh[(size_t)NG * NH];
__device__ float  g_bias[NG];
__device__ __half g_XGh[(size_t)NT * NB * NG];      // input gates, row-major [t*NB+b][4096]
__device__ __half g_hbuf[2][NB * NH];               // double-buffered h (fp16)
__device__ float  g_hidden[NB * NC];
__device__ unsigned g_bar_arrive[2];
__device__ unsigned g_bar_gen[2];

// ---------------- helpers ----------------
__device__ __forceinline__ void mma16(float* c, uint32_t a0, uint32_t a1, uint32_t a2,
                                      uint32_t a3, uint32_t b0, uint32_t b1) {
    asm("mma.sync.aligned.m16n8k16.row.col.f32.f16.f16.f32 "
        "{%0,%1,%2,%3}, {%4,%5,%6,%7}, {%8,%9}, {%0,%1,%2,%3};\n"
        : "+f"(c[0]), "+f"(c[1]), "+f"(c[2]), "+f"(c[3])
        : "r"(a0), "r"(a1), "r"(a2), "r"(a3), "r"(b0), "r"(b1));
}

__device__ __forceinline__ float fast_sig(float x) {
    return __fdividef(1.f, 1.f + __expf(-x));
}
__device__ __forceinline__ float fast_tanh(float x) {
    return 1.f - __fdividef(2.f, __expf(2.f * x) + 1.f);
}

__device__ __forceinline__ uint32_t smem_u32(const void* p) {
    uint32_t a;
    asm("{ .reg .u64 t; cvta.to.shared.u64 t, %1; cvt.u32.u64 %0, t; }" : "=r"(a) : "l"(p));
    return a;
}

// ---------------- packing / init ----------------
__global__ void pack_x(const float* __restrict__ xt, const float* __restrict__ xa,
                       const float* __restrict__ xv) {
    size_t idx = (size_t)blockIdx.x * blockDim.x + threadIdx.x;
    int d = (int)(idx % KP);
    size_t r = idx / KP;             // r = t*NB + b
    int t = (int)(r / NB), b = (int)(r % NB);
    float v = 0.f;
    if (d < D_T)            v = xt[((size_t)b * NT + t) * D_T + d];
    else if (d < D_T + D_A) v = xa[((size_t)b * NT + t) * D_A + (d - D_T)];
    else if (d < DD)        v = xv[((size_t)b * NT + t) * D_V + (d - D_T - D_A)];
    g_Xh[idx] = __float2half(v);
}

__global__ void pack_wih(const float* __restrict__ W) {
    size_t idx = (size_t)blockIdx.x * blockDim.x + threadIdx.x;
    int d = (int)(idx % KP);
    size_t row = idx / KP;
    float v = (d < DD) ? W[row * DD + d] : 0.f;
    g_Wihh[idx] = __float2half(v);
}

__global__ void pack_whh(const float* __restrict__ W) {
    size_t idx = (size_t)blockIdx.x * blockDim.x + threadIdx.x;
    g_Whhh[idx] = __float2half(W[idx]);
}

__global__ void pack_bias(const float* __restrict__ bih, const float* __restrict__ bhh) {
    int i = blockIdx.x * blockDim.x + threadIdx.x;
    g_bias[i] = bih[i] + bhh[i];
}

__global__ void zero_state() {
    int i = blockIdx.x * blockDim.x + threadIdx.x;
    ((__half*)g_hbuf)[i] = __float2half(0.f);
    if (i < 2) { g_bar_arrive[i] = 0u; g_bar_gen[i] = 0u; }
}

// ---------------- Phase A: XG = X @ Wih^T + bias (fp16, 3-stage cp.async, BK=32) ----------------
// M=65536, N=4096, K=416. BM=128, BN=128, BK=32, 256 threads (2x4 warps, 64x32 tiles).
__global__ __launch_bounds__(256, 2) void gemm_xg() {
    extern __shared__ __align__(16) __half dsmA[];
    __half (*As)[128][40] = (__half (*)[128][40])dsmA;                 // 3 stages
    __half (*Bs)[128][40] = (__half (*)[128][40])(dsmA + 3 * XA_STAGE);

    const int tid = threadIdx.x;
    const int warp = tid >> 5, lane = tid & 31;
    const int gid = lane >> 2, tig = lane & 3;
    const int wm = warp >> 2, wn = warp & 3;
    const int mbase = blockIdx.y * 128;
    const int nbase = blockIdx.x * 128;

    float acc[4][4][4];
#pragma unroll
    for (int i = 0; i < 4; i++)
#pragma unroll
        for (int j = 0; j < 4; j++)
#pragma unroll
            for (int k = 0; k < 4; k++) acc[i][j][k] = 0.f;

    // cp.async plan: 4 x 16B segments per thread (A: 512 segs, B: 512 segs)
    const __half* srcP[4];
    uint32_t dstP[4];
#pragma unroll
    for (int i = 0; i < 4; i++) {
        const int seg = tid + 256 * i;
        if (seg < 512) {
            const int row = seg >> 2, q = seg & 3;
            srcP[i] = g_Xh + (size_t)(mbase + row) * KP + q * 8;
            dstP[i] = smem_u32(&As[0][row][q * 8]);
        } else {
            const int s2 = seg - 512;
            const int row = s2 >> 2, q = s2 & 3;
            srcP[i] = g_Wihh + (size_t)(nbase + row) * KP + q * 8;
            dstP[i] = smem_u32(&Bs[0][row][q * 8]);
        }
    }
    const uint32_t stB = XA_STAGE * 2;   // bytes per stage

#define CPXA(kc_) do {                                                              \
    _Pragma("unroll")                                                               \
    for (int i_ = 0; i_ < 4; i_++)                                                  \
        asm volatile("cp.async.cg.shared.global [%0], [%1], 16;\n"                  \
                     :: "r"(dstP[i_] + ((kc_) % 3) * stB), "l"(srcP[i_] + (kc_) * 32)); \
    asm volatile("cp.async.commit_group;\n" ::: "memory");                          \
} while (0)

    CPXA(0);
    CPXA(1);

    const int NKA = KP / 32;   // 13
    for (int kc = 0; kc < NKA; kc++) {
        if (kc + 2 < NKA) asm volatile("cp.async.wait_group 1;\n" ::: "memory");
        else              asm volatile("cp.async.wait_group 0;\n" ::: "memory");
        __syncthreads();
        if (kc + 2 < NKA) CPXA(kc + 2);

        const int cur = kc % 3;
#pragma unroll
        for (int s = 0; s < 2; s++) {
            const int ko = s * 16;
            uint32_t a[4][4], bf[4][2];
#pragma unroll
            for (int mt = 0; mt < 4; mt++) {
                const int rr = wm * 64 + mt * 16 + gid;
                a[mt][0] = *(const uint32_t*)(&As[cur][rr][ko + 2 * tig]);
                a[mt][1] = *(const uint32_t*)(&As[cur][rr + 8][ko + 2 * tig]);
                a[mt][2] = *(const uint32_t*)(&As[cur][rr][ko + 2 * tig + 8]);
                a[mt][3] = *(const uint32_t*)(&As[cur][rr + 8][ko + 2 * tig + 8]);
            }
#pragma unroll
            for (int nt = 0; nt < 4; nt++) {
                const int nn = wn * 32 + nt * 8 + gid;
                bf[nt][0] = *(const uint32_t*)(&Bs[cur][nn][ko + 2 * tig]);
                bf[nt][1] = *(const uint32_t*)(&Bs[cur][nn][ko + 2 * tig + 8]);
            }
#pragma unroll
            for (int mt = 0; mt < 4; mt++)
#pragma unroll
                for (int nt = 0; nt < 4; nt++)
                    mma16(acc[mt][nt], a[mt][0], a[mt][1], a[mt][2], a[mt][3],
                          bf[nt][0], bf[nt][1]);
        }
        // no trailing __syncthreads: next iteration's top barrier orders stage reuse
    }
#undef CPXA

#pragma unroll
    for (int mt = 0; mt < 4; mt++) {
        const int row = mbase + wm * 64 + mt * 16 + gid;
#pragma unroll
        for (int nt = 0; nt < 4; nt++) {
            const int col = nbase + wn * 32 + nt * 8 + 2 * tig;
            const float b0 = g_bias[col], b1 = g_bias[col + 1];
            __half2 v0 = __floats2half2_rn(acc[mt][nt][0] + b0, acc[mt][nt][1] + b1);
            __half2 v1 = __floats2half2_rn(acc[mt][nt][2] + b0, acc[mt][nt][3] + b1);
            *(__half2*)(&g_XGh[(size_t)row * NG + col]) = v0;
            *(__half2*)(&g_XGh[(size_t)(row + 8) * NG + col]) = v1;
        }
    }
}

// ---------------- persistent recurrence kernel ----------------
// 128 CTAs, 512 threads (16 warps: wm 0..7 x wn 0..1). CTA = 128 batch x 16 h-cols.
// Whh slice resident in smem; c in registers; h double-buffered in gmem;
// K pipelined in 64-half chunks (4 stages, 3 in flight);
// per-batch-half grid barrier (two independent 64-CTA groups).
__global__ __launch_bounds__(512, 1) void lstm_rec() {
    extern __shared__ __align__(16) __half dsm[];
    __half (*As)[128][APITCH] = (__half (*)[128][APITCH])dsm;          // NASTG stages
    __half (*Bs)[BPITCH] = (__half (*)[BPITCH])(dsm + NASTG * ASTAGE);

    const int tid = threadIdx.x;
    const int warp = tid >> 5, lane = tid & 31;
    const int gid = lane >> 2, tig = lane & 3;
    const int wm = warp >> 1;          // 0..7 : 16-row slices
    const int wn = warp & 1;           // 0..1 : 8 h-cols each
    const int blk = blockIdx.x;
    const int nbase = (blk & 63) * 16;     // h-col base
    const int mbase = (blk >> 6) * 128;    // batch base
    const int grp = blk >> 6;              // independent barrier group per batch half

    // ---- load Whh slice into smem once (64 rows x 1024 halves) ----
    for (int q = tid; q < 64 * 128; q += 512) {
        const int j = q >> 7, seg = q & 127;          // j: gate*16+col
        const int gate = j >> 4, col = nbase + (j & 15);
        *(uint4*)(&Bs[j][seg * 8]) =
            *(const uint4*)(g_Whhh + (size_t)(gate * NH + col) * NH + seg * 8);
    }
    __syncthreads();

    // ---- cp.async plan for A: 2 x 16B segments per thread per 64-half chunk ----
    uint32_t dstA[2];
    size_t aoff[2];
#pragma unroll
    for (int i = 0; i < 2; i++) {
        const int seg = tid + 512 * i;                // 0..1023
        const int row = seg >> 3, q = seg & 7;        // 8 segs of 16B per row
        dstA[i] = smem_u32(&As[0][row][q * 8]);
        aoff[i] = (size_t)(mbase + row) * NH + q * 8;
    }
    const uint32_t stA = ASTAGE * 2;   // bytes per A stage

    const int rr0 = wm * 16 + gid;
    const int row0 = mbase + rr0;
    const int nc = nbase + wn * 8 + 2 * tig;

    float creg[4];
#pragma unroll
    for (int p = 0; p < 4; p++) creg[p] = 0.f;

    for (int t = 0; t < NT; t++) {
        const __half* hR = g_hbuf[t & 1];
        __half* hW = g_hbuf[(t + 1) & 1];

        // prefetch XG gate values (hidden under K-loop)
        __half2 xg0[4], xg1[4];
        {
            const size_t b0 = ((size_t)t * NB + row0) * NG + nc;
            const size_t b1 = ((size_t)t * NB + row0 + 8) * NG + nc;
#pragma unroll
            for (int g = 0; g < 4; g++) {
                xg0[g] = __ldg((const __half2*)&g_XGh[b0 + g * 1024]);
                xg1[g] = __ldg((const __half2*)&g_XGh[b1 + g * 1024]);
            }
        }

#define CPA(kc_) do {                                                               \
        _Pragma("unroll")                                                           \
        for (int i_ = 0; i_ < 2; i_++)                                              \
            asm volatile("cp.async.cg.shared.global [%0], [%1], 16;\n"              \
                         :: "r"(dstA[i_] + ((kc_) % NASTG) * stA),                  \
                            "l"(hR + aoff[i_] + (kc_) * 64));                       \
        asm volatile("cp.async.commit_group;\n" ::: "memory");                      \
} while (0)

        CPA(0);
        CPA(1);
        CPA(2);

        float acc[4][4];
#pragma unroll
        for (int g = 0; g < 4; g++)
#pragma unroll
            for (int k = 0; k < 4; k++) acc[g][k] = 0.f;

        const int NITER = 16;
        for (int kc = 0; kc < NITER; kc++) {
            if (kc + 3 <= NITER) asm volatile("cp.async.wait_group 2;\n" ::: "memory");
            else if (kc + 2 == NITER) asm volatile("cp.async.wait_group 1;\n" ::: "memory");
            else                 asm volatile("cp.async.wait_group 0;\n" ::: "memory");
            __syncthreads();
            if (kc + 3 < NITER) CPA(kc + 3);

            const int cur = kc % NASTG;
#pragma unroll
            for (int s = 0; s < 4; s++) {
                const int ko = s * 16;
                uint32_t a0, a1, a2, a3;
                a0 = *(const uint32_t*)(&As[cur][rr0][ko + 2 * tig]);
                a1 = *(const uint32_t*)(&As[cur][rr0 + 8][ko + 2 * tig]);
                a2 = *(const uint32_t*)(&As[cur][rr0][ko + 2 * tig + 8]);
                a3 = *(const uint32_t*)(&As[cur][rr0 + 8][ko + 2 * tig + 8]);
                const int kg = kc * 64 + ko;
#pragma unroll
                for (int g = 0; g < 4; g++) {
                    const int nb = g * 16 + wn * 8 + gid;
                    const uint32_t b0 = *(const uint32_t*)(&Bs[nb][kg + 2 * tig]);
                    const uint32_t b1 = *(const uint32_t*)(&Bs[nb][kg + 2 * tig + 8]);
                    mma16(acc[g], a0, a1, a2, a3, b0, b1);
                }
            }
            // no trailing __syncthreads: 4-stage ring + next top barrier protect reuse
        }
#undef CPA

        // ---- pointwise LSTM update (all 4 gates thread-local) ----
        {
            float hv[4];
#pragma unroll
            for (int p = 0; p < 4; p++) {
                const __half2* xg = (p < 2) ? xg0 : xg1;
                const int e = p & 1;
                const float xi = e ? __high2float(xg[0]) : __low2float(xg[0]);
                const float xf = e ? __high2float(xg[1]) : __low2float(xg[1]);
                const float xs = e ? __high2float(xg[2]) : __low2float(xg[2]);
                const float xo = e ? __high2float(xg[3]) : __low2float(xg[3]);
                const float iv = fast_sig(acc[0][p] + xi);
                const float fv = fast_sig(acc[1][p] + xf);
                const float gv = fast_tanh(acc[2][p] + xs);
                const float ov = fast_sig(acc[3][p] + xo);
                const float cn = fv * creg[p] + iv * gv;
                creg[p] = cn;
                hv[p] = ov * fast_tanh(cn);
            }
            *(__half2*)(&hW[(size_t)row0 * NH + nc]) = __floats2half2_rn(hv[0], hv[1]);
            *(__half2*)(&hW[(size_t)(row0 + 8) * NH + nc]) = __floats2half2_rn(hv[2], hv[3]);
        }

        // ---- per-batch-half grid barrier (64 CTAs; skip after last step) ----
        if (t + 1 < NT) {
            __syncthreads();
            if (tid == 0) {
                __threadfence();
                const unsigned old = atomicAdd(&g_bar_arrive[grp], 1u);
                if (old == NGRP - 1) {
                    g_bar_arrive[grp] = 0u;
                    __threadfence();
                    atomicAdd(&g_bar_gen[grp], 1u);
                } else {
                    const unsigned target = (unsigned)(t + 1);
                    while (*((volatile unsigned*)&g_bar_gen[grp]) < target) {}
                }
                __threadfence();
            }
            __syncthreads();
        }
    }
}

// ---------------- MLP head ----------------
__global__ void mlp1(const float* __restrict__ W1, const float* __restrict__ b1) {
    const int b = blockIdx.y * 32 + threadIdx.x;
    const int c = blockIdx.x * 8 + threadIdx.y;
    const __half* hr = g_hbuf[0] + (size_t)b * NH;   // final h lands in buffer 0 (NT even)
    const float* wr = W1 + (size_t)c * NH;
    float s = 0.f;
#pragma unroll 4
    for (int k = 0; k < NH; k++) s += __half2float(hr[k]) * wr[k];
    g_hidden[(size_t)b * NC + c] = fmaxf(s + b1[c], 0.f);
}

__global__ void mlp2(const float* __restrict__ W2, const float* __restrict__ b2,
                     float* __restrict__ out) {
    const int b = blockIdx.x;
    const int tid = threadIdx.x;  // 128
    float s = 0.f;
    for (int c = tid; c < NC; c += 128) s += g_hidden[b * NC + c] * W2[c];
#pragma unroll
    for (int o = 16; o > 0; o >>= 1) s += __shfl_down_sync(0xffffffffu, s, o);
    __shared__ float red[4];
    if ((tid & 31) == 0) red[tid >> 5] = s;
    __syncthreads();
    if (tid == 0) out[b] = red[0] + red[1] + red[2] + red[3] + b2[0];
}

// ---------------- launch ----------------
extern "C" void kernel_launch(void* const* d_in, const int* in_sizes, int n_in,
                              void* d_out, int out_size) {
    const float* x_text = (const float*)d_in[0];
    const float* x_audio = (const float*)d_in[1];
    const float* x_vision = (const float*)d_in[2];
    const float* W_ih = (const float*)d_in[3];
    const float* W_hh = (const float*)d_in[4];
    const float* b_ih = (const float*)d_in[5];
    const float* b_hh = (const float*)d_in[6];
    const float* W1 = (const float*)d_in[7];
    const float* b1 = (const float*)d_in[8];
    const float* W2 = (const float*)d_in[9];
    const float* b2 = (const float*)d_in[10];
    float* out = (float*)d_out;

    static int s_attr_done = 0;
    if (!s_attr_done) {
        cudaFuncSetAttribute(lstm_rec, cudaFuncAttributeMaxDynamicSharedMemorySize,
                             REC_SMEM);
        cudaFuncSetAttribute(gemm_xg, cudaFuncAttributeMaxDynamicSharedMemorySize,
                             XA_SMEM);
        s_attr_done = 1;
    }

    pack_x<<<(int)(((size_t)NB * NT * KP) / 256), 256>>>(x_text, x_audio, x_vision);
    pack_wih<<<(NG * KP) / 256, 256>>>(W_ih);
    pack_whh<<<(NG * NH) / 256, 256>>>(W_hh);
    pack_bias<<<NG / 256, 256>>>(b_ih, b_hh);
    zero_state<<<(2 * NB * NH) / 256, 256>>>();

    gemm_xg<<<dim3(32, 512), 256, XA_SMEM>>>();

    lstm_rec<<<NCTA_REC, 512, REC_SMEM>>>();

    mlp1<<<dim3(64, 8), dim3(32, 8)>>>(W1, b1);
    mlp2<<<NB, 128>>>(W2, b2, out);
}